// round 5
// baseline (speedup 1.0000x reference)
#include <cuda_runtime.h>
#include <math.h>

#define QT   128   // queries per block == threads per block (1 thread : 1 query)
#define KT   32    // keys per shared-memory tile
#define CH   8     // score chunk (bounds live score registers, amortizes rescale)
#define DK   64
#define SLEN 2048
#define HH   16

__device__ __forceinline__ float ex2f(float x) {
    float y;
    asm("ex2.approx.ftz.f32 %0, %1;" : "=f"(y) : "f"(x));
    return y;
}

__global__ __launch_bounds__(QT, 1) void attn_kernel(
    const float* __restrict__ q, const float* __restrict__ k,
    const float* __restrict__ v, const int* __restrict__ layer_idx,
    float* __restrict__ out)
{
    __shared__ float Ks[KT][DK];
    __shared__ float Vs[KT][DK];

    const int h  = blockIdx.y;
    const int q0 = blockIdx.x * QT;
    const int i  = q0 + threadIdx.x;                 // this thread's query row
    const int win = ((layer_idx[0] & 1) == 0) ? SLEN : 256;

    // fold 1/sqrt(dk) and log2(e) into the score so softmax runs in base 2
    const float sc = 0.125f * 1.44269504088896341f;

    const float* qh = q + ((size_t)h * SLEN + i) * DK;
    const float* kh = k + (size_t)h * SLEN * DK;
    const float* vh = v + (size_t)h * SLEN * DK;

    float qr[DK];
#pragma unroll
    for (int d4 = 0; d4 < DK / 4; ++d4) {
        float4 t = reinterpret_cast<const float4*>(qh)[d4];
        qr[4*d4+0] = t.x; qr[4*d4+1] = t.y; qr[4*d4+2] = t.z; qr[4*d4+3] = t.w;
    }
    float o[DK];
#pragma unroll
    for (int d = 0; d < DK; ++d) o[d] = 0.f;
    float m = -INFINITY, l = 0.f;

    // key range this block must touch
    int blk_lo = q0 - win + 1; if (blk_lo < 0) blk_lo = 0;
    blk_lo &= ~(KT - 1);                              // align down to tile
    const int blk_hi = q0 + QT - 1;                   // inclusive; < SLEN

    // key range this WARP needs (queries within a warp differ by <=31)
    const int w0 = q0 + (threadIdx.x & ~31);
    int w_lo = w0 - win + 1; if (w_lo < 0) w_lo = 0;
    const int w_hi = w0 + 31;

    for (int t0 = blk_lo; t0 <= blk_hi; t0 += KT) {
        __syncthreads();   // protect smem from previous iteration's readers
        // cooperative tile load: KT*DK floats = 512 float4 / 128 threads = 4 each
#pragma unroll
        for (int r = 0; r < (KT * DK / 4) / QT; ++r) {
            int f   = threadIdx.x + QT * r;   // float4 index within tile
            int row = f >> 4;                 // f / (DK/4)
            int c4  = f & 15;
            int j   = t0 + row;               // always in [0, SLEN)
            reinterpret_cast<float4*>(&Ks[row][0])[c4] =
                reinterpret_cast<const float4*>(kh + (size_t)j * DK)[c4];
            reinterpret_cast<float4*>(&Vs[row][0])[c4] =
                reinterpret_cast<const float4*>(vh + (size_t)j * DK)[c4];
        }
        __syncthreads();

        // warp-level skip of tiles fully outside this warp's window
        if (t0 > w_hi || t0 + KT - 1 < w_lo) continue;

        for (int c0 = 0; c0 < KT; c0 += CH) {
            float s[CH];
            float cmax = -INFINITY;
#pragma unroll
            for (int jj = 0; jj < CH; ++jj) {
                const int j = t0 + c0 + jj;
                float a0 = 0.f, a1 = 0.f, a2 = 0.f, a3 = 0.f;
#pragma unroll
                for (int d4 = 0; d4 < DK / 4; ++d4) {
                    float4 kk = reinterpret_cast<const float4*>(&Ks[c0 + jj][0])[d4];
                    a0 = fmaf(qr[4*d4+0], kk.x, a0);
                    a1 = fmaf(qr[4*d4+1], kk.y, a1);
                    a2 = fmaf(qr[4*d4+2], kk.z, a2);
                    a3 = fmaf(qr[4*d4+3], kk.w, a3);
                }
                const float acc = (a0 + a1) + (a2 + a3);
                const bool valid = (j <= i) && (i - j < win);
                s[jj] = valid ? acc * sc : -INFINITY;
                cmax = fmaxf(cmax, s[jj]);
            }
            if (cmax == -INFINITY) continue;          // whole chunk masked

            const float mnew = fmaxf(m, cmax);
            const float fsc  = ex2f(m - mnew);        // m==-inf -> 0 (correct)
            m = mnew;
            l *= fsc;
#pragma unroll
            for (int d = 0; d < DK; ++d) o[d] *= fsc;

#pragma unroll
            for (int jj = 0; jj < CH; ++jj) {
                const float p = ex2f(s[jj] - mnew);   // masked -> exp2(-inf)=0
                l += p;
#pragma unroll
                for (int d4 = 0; d4 < DK / 4; ++d4) {
                    float4 vv = reinterpret_cast<const float4*>(&Vs[c0 + jj][0])[d4];
                    o[4*d4+0] = fmaf(p, vv.x, o[4*d4+0]);
                    o[4*d4+1] = fmaf(p, vv.y, o[4*d4+1]);
                    o[4*d4+2] = fmaf(p, vv.z, o[4*d4+2]);
                    o[4*d4+3] = fmaf(p, vv.w, o[4*d4+3]);
                }
            }
        }
    }

    const float inv = 1.f / l;                         // diagonal always valid -> l>0
    float* op = out + ((size_t)h * SLEN + i) * DK;
#pragma unroll
    for (int d4 = 0; d4 < DK / 4; ++d4) {
        float4 t;
        t.x = o[4*d4+0] * inv; t.y = o[4*d4+1] * inv;
        t.z = o[4*d4+2] * inv; t.w = o[4*d4+3] * inv;
        reinterpret_cast<float4*>(op)[d4] = t;
    }
}

extern "C" void kernel_launch(void* const* d_in, const int* in_sizes, int n_in,
                              void* d_out, int out_size)
{
    const float* q = (const float*)d_in[0];
    const float* k = (const float*)d_in[1];
    const float* v = (const float*)d_in[2];
    const int* layer_idx = (const int*)d_in[3];
    // d_in[4] = training (unused; reference is deterministic for training=0)

    float* out = (float*)d_out;
    const size_t n = (size_t)out_size / 3;   // context | k | v, each B*H*S*DK

    dim3 grid(SLEN / QT, HH);
    attn_kernel<<<grid, QT>>>(q, k, v, layer_idx, out);

    // present = (k, v) passthrough
    cudaMemcpyAsync(out + n,     k, n * sizeof(float), cudaMemcpyDeviceToDevice);
    cudaMemcpyAsync(out + 2 * n, v, n * sizeof(float), cudaMemcpyDeviceToDevice);
}

// round 7
// speedup vs baseline: 1.0291x; 1.0291x over previous
#include <cuda_runtime.h>
#include <math.h>

typedef unsigned long long u64;

#define QT   128   // queries per block == threads per block (1 thread : 1 query)
#define KT   64    // keys per shared-memory tile
#define CH   8     // score chunk
#define DK   64
#define SLEN 2048
#define HH   16

__device__ __forceinline__ float ex2f(float x) {
    float y; asm("ex2.approx.ftz.f32 %0, %1;" : "=f"(y) : "f"(x)); return y;
}
// packed f32x2 ops (Blackwell): one issue, two fp32 lanes
__device__ __forceinline__ u64 ffma2(u64 a, u64 b, u64 c) {
    u64 r; asm("fma.rn.f32x2 %0, %1, %2, %3;" : "=l"(r) : "l"(a), "l"(b), "l"(c)); return r;
}
__device__ __forceinline__ u64 fadd2(u64 a, u64 b) {
    u64 r; asm("add.rn.f32x2 %0, %1, %2;" : "=l"(r) : "l"(a), "l"(b)); return r;
}
__device__ __forceinline__ u64 fmul2(u64 a, u64 b) {
    u64 r; asm("mul.rn.f32x2 %0, %1, %2;" : "=l"(r) : "l"(a), "l"(b)); return r;
}
__device__ __forceinline__ u64 pack2(float lo, float hi) {
    u64 r; asm("mov.b64 %0, {%1, %2};" : "=l"(r) : "f"(lo), "f"(hi)); return r;
}
__device__ __forceinline__ float2 unpack2(u64 d) {
    float lo, hi; asm("mov.b64 {%0, %1}, %2;" : "=f"(lo), "=f"(hi) : "l"(d));
    return make_float2(lo, hi);
}

__global__ __launch_bounds__(QT, 1) void attn_kernel(
    const float* __restrict__ q, const float* __restrict__ k,
    const float* __restrict__ v, const int* __restrict__ layer_idx,
    float* __restrict__ out)
{
    __shared__ float Ks[KT][DK];
    __shared__ float Vs[KT][DK];

    const int h  = blockIdx.y;
    const int q0 = blockIdx.x * QT;
    const int i  = q0 + threadIdx.x;
    const int win = ((layer_idx[0] & 1) == 0) ? SLEN : 256;

    const float sc = 0.125f * 1.44269504088896341f;  // 1/sqrt(64) * log2(e)

    const float* qh = q + ((size_t)h * SLEN + i) * DK;
    const float* kh = k + (size_t)h * SLEN * DK;
    const float* vh = v + (size_t)h * SLEN * DK;

    const size_t n = (size_t)HH * SLEN * DK;  // elements per tensor in out

    // ---- fold present=(k,v) passthrough into the kernel (overlaps compute) ----
    {
        const float4* ksrc = (const float4*)(kh + (size_t)i * DK);
        const float4* vsrc = (const float4*)(vh + (size_t)i * DK);
        float4* kdst = (float4*)(out + n     + ((size_t)h * SLEN + i) * DK);
        float4* vdst = (float4*)(out + 2 * n + ((size_t)h * SLEN + i) * DK);
#pragma unroll
        for (int t = 0; t < DK / 4; ++t) { kdst[t] = ksrc[t]; vdst[t] = vsrc[t]; }
    }

    // q row, packed as 32 f32x2 pairs
    u64 q2[DK / 2];
    {
        const ulonglong2* qp = (const ulonglong2*)qh;
#pragma unroll
        for (int t = 0; t < DK / 4; ++t) {
            ulonglong2 w = qp[t];
            q2[2 * t] = w.x; q2[2 * t + 1] = w.y;
        }
    }
    u64 o2[DK / 2];
#pragma unroll
    for (int t = 0; t < DK / 2; ++t) o2[t] = 0ull;   // bit pattern 0 == {0.f,0.f}
    float m = -INFINITY, l = 0.f;

    // block key range
    int blk_lo = q0 - win + 1; if (blk_lo < 0) blk_lo = 0;
    blk_lo &= ~(KT - 1);
    const int blk_hi = q0 + QT - 1;

    // this warp's key range (queries within a warp differ by <=31)
    const int w0 = q0 + (threadIdx.x & ~31);
    int w_lo = w0 - win + 1; if (w_lo < 0) w_lo = 0;
    const int w_hi = w0 + 31;

    for (int t0 = blk_lo; t0 <= blk_hi; t0 += KT) {
        __syncthreads();
        // cooperative tile load: KT*DK*2 floats = 2048 float4 / 128 threads = 16 each
#pragma unroll
        for (int r = 0; r < (KT * DK / 4) / QT; ++r) {
            int f   = threadIdx.x + QT * r;
            int row = f >> 4;          // f / (DK/4)
            int c4  = f & 15;
            int j   = t0 + row;        // always in [0, SLEN)
            reinterpret_cast<float4*>(&Ks[row][0])[c4] =
                reinterpret_cast<const float4*>(kh + (size_t)j * DK)[c4];
            reinterpret_cast<float4*>(&Vs[row][0])[c4] =
                reinterpret_cast<const float4*>(vh + (size_t)j * DK)[c4];
        }
        __syncthreads();

        if (t0 > w_hi || t0 + KT - 1 < w_lo) continue;  // warp-level tile skip

        for (int c0 = 0; c0 < KT; c0 += CH) {
            float s[CH];
            float cmax = -INFINITY;
#pragma unroll
            for (int jj = 0; jj < CH; ++jj) {
                const int j = t0 + c0 + jj;
                const ulonglong2* kr = (const ulonglong2*)&Ks[c0 + jj][0];
                u64 a0 = 0ull, a1 = 0ull, a2 = 0ull, a3 = 0ull;
#pragma unroll
                for (int t = 0; t < DK / 8; ++t) {     // 8 iters, 4 pairs each
                    ulonglong2 ka = kr[2 * t];
                    ulonglong2 kb = kr[2 * t + 1];
                    a0 = ffma2(q2[4 * t + 0], ka.x, a0);
                    a1 = ffma2(q2[4 * t + 1], ka.y, a1);
                    a2 = ffma2(q2[4 * t + 2], kb.x, a2);
                    a3 = ffma2(q2[4 * t + 3], kb.y, a3);
                }
                float2 rr = unpack2(fadd2(fadd2(a0, a1), fadd2(a2, a3)));
                const float acc = rr.x + rr.y;
                const bool valid = (j <= i) && (i - j < win);
                s[jj] = valid ? acc * sc : -INFINITY;
                cmax = fmaxf(cmax, s[jj]);
            }
            if (cmax == -INFINITY) continue;   // warp-uniform in masked regions

            const float mnew = fmaxf(m, cmax);
            const float fsc  = ex2f(m - mnew);  // m==-inf -> 0 (correct)
            m = mnew;
            l *= fsc;
            const u64 ff = pack2(fsc, fsc);
#pragma unroll
            for (int t = 0; t < DK / 2; ++t) o2[t] = fmul2(o2[t], ff);

#pragma unroll
            for (int jj = 0; jj < CH; ++jj) {
                const float p = ex2f(s[jj] - mnew);   // masked -> 0
                l += p;
                const u64 pp = pack2(p, p);
                const ulonglong2* vr = (const ulonglong2*)&Vs[c0 + jj][0];
#pragma unroll
                for (int t = 0; t < DK / 4; ++t) {
                    ulonglong2 vv = vr[t];
                    o2[2 * t]     = ffma2(pp, vv.x, o2[2 * t]);
                    o2[2 * t + 1] = ffma2(pp, vv.y, o2[2 * t + 1]);
                }
            }
        }
    }

    const float inv = 1.f / l;   // diagonal always valid -> l > 0
    float* op = out + ((size_t)h * SLEN + i) * DK;
#pragma unroll
    for (int t = 0; t < DK / 4; ++t) {
        float2 x = unpack2(o2[2 * t]);
        float2 y = unpack2(o2[2 * t + 1]);
        float4 r;
        r.x = x.x * inv; r.y = x.y * inv;
        r.z = y.x * inv; r.w = y.y * inv;
        reinterpret_cast<float4*>(op)[t] = r;
    }
}

extern "C" void kernel_launch(void* const* d_in, const int* in_sizes, int n_in,
                              void* d_out, int out_size)
{
    const float* q = (const float*)d_in[0];
    const float* k = (const float*)d_in[1];
    const float* v = (const float*)d_in[2];
    const int* layer_idx = (const int*)d_in[3];
    // d_in[4] = training (unused; deterministic path)

    float* out = (float*)d_out;

    dim3 grid(SLEN / QT, HH);
    attn_kernel<<<grid, QT>>>(q, k, v, layer_idx, out);
}